// round 10
// baseline (speedup 1.0000x reference)
#include <cuda_runtime.h>
#include <cuda_bf16.h>
#include <stdint.h>

// OptimizerNetwork: 2-layer LSTM-cell meta-optimizer, N=1e6 rows, H=20.
// R7 (HMMA bf16 hi/lo x3, 163us) plateaued latency-bound: 168 regs (80 = C
// accumulators) -> 3 CTAs/SM, occ 17.5%, issue 30%, no pipe saturated.
// R10: gate-pair B permutation (ntile 2j = i,f; 2j+1 = g,o for h-group j)
// -> GEMM+epilogue per ntile-pair: C = 16 regs. Cell's A frags preloaded to
// registers once (no re-reads). 4 CTAs/SM. A stride 116->100B to fit smem.

#define TPB 128
typedef unsigned uns;

// ---- smem layout (bytes) ----
#define A_OFF     0u        // [2][128][50] bf16; row stride 100B (25 words)
#define A_STRIDE  100u
#define A_SPLIT   12800u
#define B1_OFF    25600u    // [2][80][40] bf16; row stride 80B
#define B1_STRIDE 80u
#define B1_SPLIT  6400u
#define B2_OFF    38400u    // [2][80][56] bf16; row stride 112B
#define B2_STRIDE 112u
#define B2_SPLIT  8960u
#define WOUT_OFF  56320u    // float[20]
#define BOUT_OFF  56400u    // float
#define SMEM_BYTES 56416u

__device__ __forceinline__ float tanha(float x) {
    float r; asm("tanh.approx.f32 %0, %1;" : "=f"(r) : "f"(x)); return r;
}
__device__ __forceinline__ float sigm(float x) {
    return fmaf(0.5f, tanha(0.5f * x), 0.5f);
}

// store float pair as bf16 hi/lo into both A splits (cols col,col+1; col even)
__device__ __forceinline__ void stA2(char* sm, int row, int col, float a, float b) {
    __nv_bfloat16 ah = __float2bfloat16(a), bh = __float2bfloat16(b);
    __nv_bfloat162 hv; hv.x = ah; hv.y = bh;
    __nv_bfloat162 lv;
    lv.x = __float2bfloat16(a - __bfloat162float(ah));
    lv.y = __float2bfloat16(b - __bfloat162float(bh));
    char* p = sm + A_OFF + row * A_STRIDE + col * 2;
    *(__nv_bfloat162*)p = hv;
    *(__nv_bfloat162*)(p + A_SPLIT) = lv;
}
__device__ __forceinline__ void stA1(char* sm, int row, int col, float a) {
    __nv_bfloat16 h = __float2bfloat16(a);
    char* p = sm + A_OFF + row * A_STRIDE + col * 2;
    *(__nv_bfloat16*)p = h;
    *(__nv_bfloat16*)(p + A_SPLIT) = __float2bfloat16(a - __bfloat162float(h));
}
__device__ __forceinline__ void stB(char* sm, uns off, uns split, uns stride,
                                    int row, int col, float v) {
    __nv_bfloat16 h = __float2bfloat16(v);
    char* p = sm + off + row * stride + col * 2;
    *(__nv_bfloat16*)p = h;
    *(__nv_bfloat16*)(p + split) = __float2bfloat16(v - __bfloat162float(h));
}

__device__ __forceinline__ void mma16816(float* c, const uns* a, const uns* b) {
    asm volatile("mma.sync.aligned.m16n8k16.row.col.f32.bf16.bf16.f32 "
        "{%0,%1,%2,%3}, {%4,%5,%6,%7}, {%8,%9}, {%0,%1,%2,%3};"
        : "+f"(c[0]), "+f"(c[1]), "+f"(c[2]), "+f"(c[3])
        : "r"(a[0]), "r"(a[1]), "r"(a[2]), "r"(a[3]), "r"(b[0]), "r"(b[1]));
}

// A fragment: rows mbase+(l/4), +8; k = kb+(l%4)*2, +8 (scalar LDS, conflict-free)
__device__ __forceinline__ void ldA(uns* a, const char* abase, int mbase, int kb, int l) {
    const char* p = abase + (mbase + (l >> 2)) * A_STRIDE + (kb + (l & 3) * 2) * 2;
    a[0] = *(const uns*)p;
    a[1] = *(const uns*)(p + 8 * A_STRIDE);
    a[2] = *(const uns*)(p + 16);
    a[3] = *(const uns*)(p + 8 * A_STRIDE + 16);
}
__device__ __forceinline__ void ldB(uns* b, const char* bbase, uns stride,
                                    int nbase, int kb, int l) {
    const char* p = bbase + (nbase + (l >> 2)) * stride + (kb + (l & 3) * 2) * 2;
    b[0] = *(const uns*)p;
    b[1] = *(const uns*)(p + 16);
}

// 12 MMAs for one ntile-pair kstep: AhBh + AlBh + AhBl (AlBl ~2^-16 dropped)
__device__ __forceinline__ void mma_pair(float C0[2][4], float C1[2][4],
                                         const uns A[2][2][4],   // [split][mt][4]
                                         const char* bbase, uns bsplit, uns stride,
                                         int n0base, int kb, int l) {
    uns bh0[2], bh1[2], bl0[2], bl1[2];
    ldB(bh0, bbase, stride, n0base, kb, l);
    ldB(bh1, bbase, stride, n0base + 8, kb, l);
    mma16816(C0[0], A[0][0], bh0); mma16816(C0[1], A[0][1], bh0);
    mma16816(C1[0], A[0][0], bh1); mma16816(C1[1], A[0][1], bh1);
    mma16816(C0[0], A[1][0], bh0); mma16816(C0[1], A[1][1], bh0);
    mma16816(C1[0], A[1][0], bh1); mma16816(C1[1], A[1][1], bh1);
    ldB(bl0, bbase + bsplit, stride, n0base, kb, l);
    ldB(bl1, bbase + bsplit, stride, n0base + 8, kb, l);
    mma16816(C0[0], A[0][0], bl0); mma16816(C0[1], A[0][1], bl0);
    mma16816(C1[0], A[0][0], bl1); mma16816(C1[1], A[0][1], bl1);
}

__global__ void __launch_bounds__(TPB, 4)
optnet_mma(const float* __restrict__ inp,
           const float* __restrict__ h0g, const float* __restrict__ h1g,
           const float* __restrict__ c0g, const float* __restrict__ c1g,
           const float* __restrict__ Wih1, const float* __restrict__ Whh1,
           const float* __restrict__ bih1, const float* __restrict__ bhh1,
           const float* __restrict__ Wih2, const float* __restrict__ Whh2,
           const float* __restrict__ bih2, const float* __restrict__ bhh2,
           const float* __restrict__ Wout, const float* __restrict__ bout,
           float* __restrict__ out, int N)
{
    extern __shared__ char sm[];
    const int tid = threadIdx.x;
    const int wid = tid >> 5;
    const int l = tid & 31;

    // ---- prologue: zero, stage gate-pair-permuted weights + consts ----
    for (int i = tid; i < (int)(SMEM_BYTES / 16); i += TPB)
        ((float4*)sm)[i] = make_float4(0.f, 0.f, 0.f, 0.f);
    __syncthreads();

    // B row p = 16j + sub: sub<8 -> ntile 2j: h=4j+(sub>>1), i(sub even)/f(odd)
    //                      sub>=8 -> ntile 2j+1: g(even)/o(odd)
    if (tid < 80) {
        const int p = tid;
        const int j = p >> 4, sub = p & 15;
        int r;
        if (sub < 8) { int h = 4 * j + (sub >> 1); r = (sub & 1) ? 20 + h : h; }
        else { int s = sub - 8; int h = 4 * j + (s >> 1); r = (s & 1) ? 60 + h : 40 + h; }
        stB(sm, B1_OFF, B1_SPLIT, B1_STRIDE, p, 0, Wih1[r * 2 + 0]);
        stB(sm, B1_OFF, B1_SPLIT, B1_STRIDE, p, 1, Wih1[r * 2 + 1]);
        for (int k = 0; k < 20; ++k) {
            stB(sm, B1_OFF, B1_SPLIT, B1_STRIDE, p, 2 + k, Whh1[r * 20 + k]);
            stB(sm, B2_OFF, B2_SPLIT, B2_STRIDE, p, k, Wih2[r * 20 + k]);
            stB(sm, B2_OFF, B2_SPLIT, B2_STRIDE, p, 20 + k, Whh2[r * 20 + k]);
        }
        stB(sm, B1_OFF, B1_SPLIT, B1_STRIDE, p, 22, bih1[r] + bhh1[r]);
        stB(sm, B2_OFF, B2_SPLIT, B2_STRIDE, p, 40, bih2[r] + bhh2[r]);
    }
    if (tid < 20) ((float*)(sm + WOUT_OFF))[tid] = Wout[tid];
    if (tid == 0) *(float*)(sm + BOUT_OFF) = bout[0];
    // A bias col 40 (cell2) set once; cols 41..49 stay zero.
    stA2(sm, (wid << 5) | l, 40, 1.f, 0.f);
    __syncthreads();

    float woutR[5];
#pragma unroll
    for (int j = 0; j < 5; ++j)
        woutR[j] = ((const float*)(sm + WOUT_OFF))[(l & 3) + 4 * j];
    const float boutv = *(const float*)(sm + BOUT_OFF);

    // output tuple sections: out, h0n@N, h1n@21N, c0n@41N, c1n@61N
    float* h0n_out = out + (size_t)N;
    float* h1n_out = out + (size_t)N * 21;
    float* c0n_out = out + (size_t)N * 41;
    float* c1n_out = out + (size_t)N * 61;

    const char* b1base = sm + B1_OFF;
    const char* b2base = sm + B2_OFF;
    const int wrow = wid * 32;
    const int nslabs = (N + 31) / 32;
    const int twarps = gridDim.x * 4;

    for (int s = blockIdx.x * 4 + wid; s < nslabs; s += twarps) {
        const int rowbase = s * 32;

        // ---- stage A cell1: x_pre (0,1), bias (22), h0 (2..21) ----
        {
            const int grow = rowbase + l;
            float x = (grow < N) ? inp[grow] : 0.f;
            float ax = fabsf(x), pa, pb;
            if (ax >= 4.5399930e-05f) {        // exp(-10)
                pa = __logf(ax + 1e-8f) * 0.1f;
                pb = (x > 0.f) ? 1.f : -1.f;
            } else {
                pa = -1.f;
                pb = 22026.4658f * x;          // exp(10)
            }
            stA2(sm, wrow + l, 0, pa, pb);
            stA2(sm, wrow + l, 22, 1.f, 0.f);  // clobbered by h1 staging later
#pragma unroll
            for (int q = 0; q < 5; ++q) {
                const int idx = q * 32 + l;
                const int gr = idx / 5, cp = idx % 5;
                float4 v = make_float4(0.f, 0.f, 0.f, 0.f);
                if (rowbase + gr < N)
                    v = ((const float4*)(h0g + (size_t)rowbase * 20))[idx];
                stA2(sm, wrow + gr, 2 + cp * 4, v.x, v.y);
                stA2(sm, wrow + gr, 4 + cp * 4, v.z, v.w);
            }
        }
        __syncwarp();

        // ---- preload cell1 A frags to registers: [ks][split][mt][4] ----
        uns A1[2][2][2][4];
#pragma unroll
        for (int ks = 0; ks < 2; ++ks)
#pragma unroll
            for (int sp = 0; sp < 2; ++sp) {
                const char* ab = sm + A_OFF + (sp ? A_SPLIT : 0u);
                ldA(A1[ks][sp][0], ab, wrow, ks * 16, l);
                ldA(A1[ks][sp][1], ab, wrow + 16, ks * 16, l);
            }

        // ---- cell1: per ntile-pair GEMM + epilogue ----
#pragma unroll
        for (int j = 0; j < 5; ++j) {
            float C0[2][4], C1[2][4];
#pragma unroll
            for (int m = 0; m < 2; ++m)
#pragma unroll
                for (int q = 0; q < 4; ++q) { C0[m][q] = 0.f; C1[m][q] = 0.f; }
#pragma unroll
            for (int ks = 0; ks < 2; ++ks)
                mma_pair(C0, C1, A1[ks], b1base, B1_SPLIT, B1_STRIDE,
                         j * 16, ks * 16, l);
            const int h = 4 * j + (l & 3);
#pragma unroll
            for (int rs = 0; rs < 4; ++rs) {
                const int mt = rs >> 1, cb = (rs & 1) * 2;
                const int rloc = (l >> 2) + 8 * rs;
                const size_t grow = (size_t)rowbase + rloc;
                const bool ok = grow < (size_t)N;
                float I = sigm(C0[mt][cb]);
                float F = sigm(C0[mt][cb + 1]);
                float G = tanha(C1[mt][cb]);
                float O = sigm(C1[mt][cb + 1]);
                float cin = ok ? c0g[grow * 20 + h] : 0.f;
                float cn = fmaf(F, cin, I * G);
                float hn = O * tanha(cn);
                if (ok) {
                    c0n_out[grow * 20 + h] = cn;
                    h0n_out[grow * 20 + h] = hn;
                }
                stA1(sm, wrow + rloc, h, hn);      // cell2 A cols 0..19
            }
        }

        // ---- stage h1 (cols 20..39); bias col 40 persists ----
#pragma unroll
        for (int q = 0; q < 5; ++q) {
            const int idx = q * 32 + l;
            const int gr = idx / 5, cp = idx % 5;
            float4 v = make_float4(0.f, 0.f, 0.f, 0.f);
            if (rowbase + gr < N)
                v = ((const float4*)(h1g + (size_t)rowbase * 20))[idx];
            stA2(sm, wrow + gr, 20 + cp * 4, v.x, v.y);
            stA2(sm, wrow + gr, 22 + cp * 4, v.z, v.w);
        }
        __syncwarp();

        // ---- preload cell2 A frags: [ks][split][mt][4] ----
        uns A2[3][2][2][4];
#pragma unroll
        for (int ks = 0; ks < 3; ++ks)
#pragma unroll
            for (int sp = 0; sp < 2; ++sp) {
                const char* ab = sm + A_OFF + (sp ? A_SPLIT : 0u);
                ldA(A2[ks][sp][0], ab, wrow, ks * 16, l);
                ldA(A2[ks][sp][1], ab, wrow + 16, ks * 16, l);
            }

        // ---- cell2: per ntile-pair GEMM + epilogue; fold output dot ----
        float psum[4] = {0.f, 0.f, 0.f, 0.f};
#pragma unroll
        for (int j = 0; j < 5; ++j) {
            float C0[2][4], C1[2][4];
#pragma unroll
            for (int m = 0; m < 2; ++m)
#pragma unroll
                for (int q = 0; q < 4; ++q) { C0[m][q] = 0.f; C1[m][q] = 0.f; }
#pragma unroll
            for (int ks = 0; ks < 3; ++ks)
                mma_pair(C0, C1, A2[ks], b2base, B2_SPLIT, B2_STRIDE,
                         j * 16, ks * 16, l);
            const int h = 4 * j + (l & 3);
#pragma unroll
            for (int rs = 0; rs < 4; ++rs) {
                const int mt = rs >> 1, cb = (rs & 1) * 2;
                const int rloc = (l >> 2) + 8 * rs;
                const size_t grow = (size_t)rowbase + rloc;
                const bool ok = grow < (size_t)N;
                float I = sigm(C0[mt][cb]);
                float F = sigm(C0[mt][cb + 1]);
                float G = tanha(C1[mt][cb]);
                float O = sigm(C1[mt][cb + 1]);
                float cin = ok ? c1g[grow * 20 + h] : 0.f;
                float cn = fmaf(F, cin, I * G);
                float hn = O * tanha(cn);
                if (ok) {
                    c1n_out[grow * 20 + h] = cn;
                    h1n_out[grow * 20 + h] = hn;
                }
                psum[rs] = fmaf(hn, woutR[j], psum[rs]);
            }
        }
#pragma unroll
        for (int rs = 0; rs < 4; ++rs) {
            float p = psum[rs];
            p += __shfl_xor_sync(0xFFFFFFFFu, p, 1);
            p += __shfl_xor_sync(0xFFFFFFFFu, p, 2);
            const size_t grow = (size_t)rowbase + (l >> 2) + 8 * rs;
            if (grow < (size_t)N && (l & 3) == 0) out[grow] = p + boutv;
        }
        __syncwarp();   // before next iteration restages A
    }
}

extern "C" void kernel_launch(void* const* d_in, const int* in_sizes, int n_in,
                              void* d_out, int out_size)
{
    static int configured = 0;
    if (!configured) {
        cudaFuncSetAttribute(optnet_mma,
                             cudaFuncAttributeMaxDynamicSharedMemorySize,
                             SMEM_BYTES);
        configured = 1;
    }
    const int N = in_sizes[0];
    const int grid = 592;   // 4 CTAs/SM x 148 SMs, persistent
    optnet_mma<<<grid, TPB, SMEM_BYTES>>>(
        (const float*)d_in[0], (const float*)d_in[1], (const float*)d_in[2],
        (const float*)d_in[3], (const float*)d_in[4],
        (const float*)d_in[5], (const float*)d_in[6],
        (const float*)d_in[7], (const float*)d_in[8],
        (const float*)d_in[9], (const float*)d_in[10],
        (const float*)d_in[11], (const float*)d_in[12],
        (const float*)d_in[13], (const float*)d_in[14],
        (float*)d_out, N);
}

// round 11
// speedup vs baseline: 1.0814x; 1.0814x over previous
#include <cuda_runtime.h>
#include <cuda_bf16.h>
#include <stdint.h>

// OptimizerNetwork: 2-layer LSTM-cell meta-optimizer, N=1e6 rows, H=20.
// Best = R7 (163us): per-warp 32-row slab, HMMA m16n8k16 bf16 hi/lo x3 passes,
// gate-permuted B (register epilogue), bias as GEMM column, warp-local staging.
// R8-R10 variants (wide LDS, smem transpose, low-reg/4CTA) all neutral/worse:
// perf tracks critical-path latency. R11 = R7 + cp.async (LDGSTS) prefetch of
// c0/c1 slabs into per-warp smem, hiding both in-epilogue 600cyc LDG chains
// under the GEMMs. A stride 116->100B keeps 3 CTAs/SM at 66.7KB smem.

#define TPB 128
typedef unsigned uns;

// ---- smem layout (bytes) ----
#define A_OFF     0u        // [2][128][50] bf16; row stride 100B
#define A_STRIDE  100u
#define A_SPLIT   12800u
#define B1_OFF    25600u    // [2][80][40] bf16; row stride 80B
#define B1_STRIDE 80u
#define B1_SPLIT  6400u
#define B2_OFF    38400u    // [2][80][56] bf16; row stride 112B
#define B2_STRIDE 112u
#define B2_SPLIT  8960u
#define WOUT_OFF  56320u    // float[20]
#define BOUT_OFF  56400u    // float
#define CB_OFF    56416u    // 4 warps x 32x20 fp32 c-state buffer
#define SMEM_BYTES 66656u

__device__ __forceinline__ float tanha(float x) {
    float r; asm("tanh.approx.f32 %0, %1;" : "=f"(r) : "f"(x)); return r;
}
__device__ __forceinline__ float sigm(float x) {
    return fmaf(0.5f, tanha(0.5f * x), 0.5f);
}

__device__ __forceinline__ void cpa16(uns dst, const void* src, bool p) {
    if (p)
        asm volatile("cp.async.cg.shared.global [%0], [%1], 16;"
                     :: "r"(dst), "l"(src));
}
#define CP_COMMIT() asm volatile("cp.async.commit_group;" ::: "memory")
#define CP_WAIT0()  asm volatile("cp.async.wait_group 0;" ::: "memory")

// store float pair as bf16 hi/lo into both A splits (cols col,col+1; col even)
__device__ __forceinline__ void stA2(char* sm, int row, int col, float a, float b) {
    __nv_bfloat16 ah = __float2bfloat16(a), bh = __float2bfloat16(b);
    __nv_bfloat162 hv; hv.x = ah; hv.y = bh;
    __nv_bfloat162 lv;
    lv.x = __float2bfloat16(a - __bfloat162float(ah));
    lv.y = __float2bfloat16(b - __bfloat162float(bh));
    char* p = sm + A_OFF + row * A_STRIDE + col * 2;
    *(__nv_bfloat162*)p = hv;
    *(__nv_bfloat162*)(p + A_SPLIT) = lv;
}
__device__ __forceinline__ void stA1(char* sm, int row, int col, float a) {
    __nv_bfloat16 h = __float2bfloat16(a);
    char* p = sm + A_OFF + row * A_STRIDE + col * 2;
    *(__nv_bfloat16*)p = h;
    *(__nv_bfloat16*)(p + A_SPLIT) = __float2bfloat16(a - __bfloat162float(h));
}
__device__ __forceinline__ void stB(char* sm, uns off, uns split, uns stride,
                                    int row, int col, float v) {
    __nv_bfloat16 h = __float2bfloat16(v);
    char* p = sm + off + row * stride + col * 2;
    *(__nv_bfloat16*)p = h;
    *(__nv_bfloat16*)(p + split) = __float2bfloat16(v - __bfloat162float(h));
}

__device__ __forceinline__ void mma16816(float* c, const uns* a, const uns* b) {
    asm volatile("mma.sync.aligned.m16n8k16.row.col.f32.bf16.bf16.f32 "
        "{%0,%1,%2,%3}, {%4,%5,%6,%7}, {%8,%9}, {%0,%1,%2,%3};"
        : "+f"(c[0]), "+f"(c[1]), "+f"(c[2]), "+f"(c[3])
        : "r"(a[0]), "r"(a[1]), "r"(a[2]), "r"(a[3]), "r"(b[0]), "r"(b[1]));
}

__device__ __forceinline__ void ldA(uns* a, const char* abase, int mbase, int kb, int l) {
    const char* p = abase + (mbase + (l >> 2)) * A_STRIDE + (kb + (l & 3) * 2) * 2;
    a[0] = *(const uns*)p;
    a[1] = *(const uns*)(p + 8 * A_STRIDE);
    a[2] = *(const uns*)(p + 16);
    a[3] = *(const uns*)(p + 8 * A_STRIDE + 16);
}
__device__ __forceinline__ void ldB(uns* b, const char* bbase, uns stride,
                                    int nbase, int kb, int l) {
    const char* p = bbase + (nbase + (l >> 2)) * stride + (kb + (l & 3) * 2) * 2;
    b[0] = *(const uns*)p;
    b[1] = *(const uns*)(p + 16);
}

// one cell GEMM: C += A*B, 3 split passes (AhBh, AhBl, AlBh; AlBl ~2^-16 dropped)
template <int KS>
__device__ __forceinline__ void gemm(float C[10][2][4], const char* sm,
                                     uns boff, uns bsplit, uns bstride,
                                     int wrow, int l) {
#pragma unroll
    for (int n = 0; n < 10; ++n)
#pragma unroll
        for (int m = 0; m < 2; ++m)
#pragma unroll
            for (int q = 0; q < 4; ++q) C[n][m][q] = 0.f;
#pragma unroll 1
    for (int sp = 0; sp < 3; ++sp) {
        const char* abase = sm + A_OFF + ((sp == 2) ? A_SPLIT : 0u);
        const char* bbase = sm + boff + ((sp == 1) ? bsplit : 0u);
#pragma unroll
        for (int k = 0; k < KS; ++k) {
            uns a0[4], a1[4];
            ldA(a0, abase, wrow, k * 16, l);
            ldA(a1, abase, wrow + 16, k * 16, l);
#pragma unroll
            for (int n = 0; n < 10; ++n) {
                uns b[2];
                ldB(b, bbase, bstride, n * 8, k * 16, l);
                mma16816(C[n][0], a0, b);
                mma16816(C[n][1], a1, b);
            }
        }
    }
}

__global__ void __launch_bounds__(TPB, 3)
optnet_mma(const float* __restrict__ inp,
           const float* __restrict__ h0g, const float* __restrict__ h1g,
           const float* __restrict__ c0g, const float* __restrict__ c1g,
           const float* __restrict__ Wih1, const float* __restrict__ Whh1,
           const float* __restrict__ bih1, const float* __restrict__ bhh1,
           const float* __restrict__ Wih2, const float* __restrict__ Whh2,
           const float* __restrict__ bih2, const float* __restrict__ bhh2,
           const float* __restrict__ Wout, const float* __restrict__ bout,
           float* __restrict__ out, int N)
{
    extern __shared__ char sm[];
    const int tid = threadIdx.x;
    const int wid = tid >> 5;
    const int l = tid & 31;

    // ---- prologue: zero, stage gate-permuted weight tiles + consts ----
    for (int i = tid; i < (int)(SMEM_BYTES / 16); i += TPB)
        ((float4*)sm)[i] = make_float4(0.f, 0.f, 0.f, 0.f);
    __syncthreads();

    // B row p: p=2h -> i_h (W row h), 2h+1 -> f_h (20+h),
    //          40+2h -> g_h (40+h), 41+2h -> o_h (60+h)
    if (tid < 80) {
        const int p = tid;
        int h, r;
        if (p < 40) { h = p >> 1; r = (p & 1) ? 20 + h : h; }
        else { int q = p - 40; h = q >> 1; r = (q & 1) ? 60 + h : 40 + h; }
        stB(sm, B1_OFF, B1_SPLIT, B1_STRIDE, p, 0, Wih1[r * 2 + 0]);
        stB(sm, B1_OFF, B1_SPLIT, B1_STRIDE, p, 1, Wih1[r * 2 + 1]);
        for (int k = 0; k < 20; ++k) {
            stB(sm, B1_OFF, B1_SPLIT, B1_STRIDE, p, 2 + k, Whh1[r * 20 + k]);
            stB(sm, B2_OFF, B2_SPLIT, B2_STRIDE, p, k, Wih2[r * 20 + k]);
            stB(sm, B2_OFF, B2_SPLIT, B2_STRIDE, p, 20 + k, Whh2[r * 20 + k]);
        }
        stB(sm, B1_OFF, B1_SPLIT, B1_STRIDE, p, 22, bih1[r] + bhh1[r]);
        stB(sm, B2_OFF, B2_SPLIT, B2_STRIDE, p, 40, bih2[r] + bhh2[r]);
    }
    if (tid < 20) ((float*)(sm + WOUT_OFF))[tid] = Wout[tid];
    if (tid == 0) *(float*)(sm + BOUT_OFF) = bout[0];
    // A bias col 40 (cell2) set once; col 41 zeroed by the pair store.
    stA2(sm, (wid << 5) | l, 40, 1.f, 0.f);
    __syncthreads();

    float woutR[5];
#pragma unroll
    for (int j = 0; j < 5; ++j)
        woutR[j] = ((const float*)(sm + WOUT_OFF))[(l & 3) + 4 * j];
    const float boutv = *(const float*)(sm + BOUT_OFF);

    // output tuple sections: out, h0n@N, h1n@21N, c0n@41N, c1n@61N
    float* h0n_out = out + (size_t)N;
    float* h1n_out = out + (size_t)N * 21;
    float* c0n_out = out + (size_t)N * 41;
    float* c1n_out = out + (size_t)N * 61;

    const int wrow = wid * 32;
    float* cw = (float*)(sm + CB_OFF + (uns)wid * 2560u);     // 32x20 fp32
    const uns cwaddr = (uns)__cvta_generic_to_shared(cw);

    const int nslabs = (N + 31) / 32;
    const int twarps = gridDim.x * 4;
    float C[10][2][4];

    for (int s = blockIdx.x * 4 + wid; s < nslabs; s += twarps) {
        const int rowbase = s * 32;

        // ---- prefetch c0 slab into CBUF (fire-and-forget, lands under GEMM1) ----
#pragma unroll
        for (int q = 0; q < 5; ++q) {
            const int idx = q * 32 + l;
            cpa16(cwaddr + (uns)idx * 16u,
                  ((const float4*)(c0g + (size_t)rowbase * 20)) + idx,
                  rowbase + idx / 5 < N);
        }
        CP_COMMIT();

        // ---- stage A cell1: x_pre (0,1), bias (22), h0 (2..21) ----
        {
            const int grow = rowbase + l;
            float x = (grow < N) ? inp[grow] : 0.f;
            float ax = fabsf(x), pa, pb;
            if (ax >= 4.5399930e-05f) {        // exp(-10)
                pa = __logf(ax + 1e-8f) * 0.1f;
                pb = (x > 0.f) ? 1.f : -1.f;
            } else {
                pa = -1.f;
                pb = 22026.4658f * x;          // exp(10)
            }
            stA2(sm, wrow + l, 0, pa, pb);
            stA2(sm, wrow + l, 22, 1.f, 0.f);  // clobbered by h1 staging later
#pragma unroll
            for (int q = 0; q < 5; ++q) {
                const int idx = q * 32 + l;
                const int gr = idx / 5, cp = idx % 5;
                float4 v = make_float4(0.f, 0.f, 0.f, 0.f);
                if (rowbase + gr < N)
                    v = ((const float4*)(h0g + (size_t)rowbase * 20))[idx];
                stA2(sm, wrow + gr, 2 + cp * 4, v.x, v.y);
                stA2(sm, wrow + gr, 4 + cp * 4, v.z, v.w);
            }
        }
        __syncwarp();

        // ---- cell1 GEMM: K=32 ----
        gemm<2>(C, sm, B1_OFF, B1_SPLIT, B1_STRIDE, wrow, l);
        CP_WAIT0();
        __syncwarp();

        // ---- epilogue 1: cin from CBUF (LDS), h0n -> gmem + A cols 0..19 ----
#pragma unroll
        for (int rs = 0; rs < 4; ++rs) {
            const int mt = rs >> 1, cb = (rs & 1) * 2;
            const int rloc = (l >> 2) + 8 * rs;
            const size_t grow = (size_t)rowbase + rloc;
            const bool ok = grow < (size_t)N;
#pragma unroll
            for (int j = 0; j < 5; ++j) {
                const int h = (l & 3) + 4 * j;
                float I = sigm(C[j][mt][cb]);
                float F = sigm(C[j][mt][cb + 1]);
                float G = tanha(C[j + 5][mt][cb]);
                float O = sigm(C[j + 5][mt][cb + 1]);
                float cin = cw[rloc * 20 + h];
                float cn = fmaf(F, cin, I * G);
                float hn = O * tanha(cn);
                if (ok) {
                    c0n_out[grow * 20 + h] = cn;
                    h0n_out[grow * 20 + h] = hn;
                }
                stA1(sm, wrow + rloc, h, hn);
            }
        }
        __syncwarp();                          // all c0 reads done before c1 lands

        // ---- prefetch c1 into the same CBUF (lands under GEMM2) ----
#pragma unroll
        for (int q = 0; q < 5; ++q) {
            const int idx = q * 32 + l;
            cpa16(cwaddr + (uns)idx * 16u,
                  ((const float4*)(c1g + (size_t)rowbase * 20)) + idx,
                  rowbase + idx / 5 < N);
        }
        CP_COMMIT();

        // ---- stage h1 (cols 20..39); bias col 40 persists ----
#pragma unroll
        for (int q = 0; q < 5; ++q) {
            const int idx = q * 32 + l;
            const int gr = idx / 5, cp = idx % 5;
            float4 v = make_float4(0.f, 0.f, 0.f, 0.f);
            if (rowbase + gr < N)
                v = ((const float4*)(h1g + (size_t)rowbase * 20))[idx];
            stA2(sm, wrow + gr, 20 + cp * 4, v.x, v.y);
            stA2(sm, wrow + gr, 22 + cp * 4, v.z, v.w);
        }
        __syncwarp();

        // ---- cell2 GEMM: K=48 ----
        gemm<3>(C, sm, B2_OFF, B2_SPLIT, B2_STRIDE, wrow, l);
        CP_WAIT0();
        __syncwarp();

        // ---- epilogue 2: c1n, h1n, out = h1n.Wout + bout ----
#pragma unroll
        for (int rs = 0; rs < 4; ++rs) {
            const int mt = rs >> 1, cb = (rs & 1) * 2;
            const int rloc = (l >> 2) + 8 * rs;
            const size_t grow = (size_t)rowbase + rloc;
            const bool ok = grow < (size_t)N;
            float psum = 0.f;
#pragma unroll
            for (int j = 0; j < 5; ++j) {
                const int h = (l & 3) + 4 * j;
                float I = sigm(C[j][mt][cb]);
                float F = sigm(C[j][mt][cb + 1]);
                float G = tanha(C[j + 5][mt][cb]);
                float O = sigm(C[j + 5][mt][cb + 1]);
                float cin = cw[rloc * 20 + h];
                float cn = fmaf(F, cin, I * G);
                float hn = O * tanha(cn);
                if (ok) {
                    c1n_out[grow * 20 + h] = cn;
                    h1n_out[grow * 20 + h] = hn;
                }
                psum = fmaf(hn, woutR[j], psum);
            }
            psum += __shfl_xor_sync(0xFFFFFFFFu, psum, 1);
            psum += __shfl_xor_sync(0xFFFFFFFFu, psum, 2);
            if (ok && (l & 3) == 0) out[grow] = psum + boutv;
        }
        __syncwarp();   // before next iteration restages A/CBUF
    }
}

extern "C" void kernel_launch(void* const* d_in, const int* in_sizes, int n_in,
                              void* d_out, int out_size)
{
    static int configured = 0;
    if (!configured) {
        cudaFuncSetAttribute(optnet_mma,
                             cudaFuncAttributeMaxDynamicSharedMemorySize,
                             SMEM_BYTES);
        configured = 1;
    }
    const int N = in_sizes[0];
    const int grid = 444;   // 3 CTAs/SM x 148 SMs, persistent
    optnet_mma<<<grid, TPB, SMEM_BYTES>>>(
        (const float*)d_in[0], (const float*)d_in[1], (const float*)d_in[2],
        (const float*)d_in[3], (const float*)d_in[4],
        (const float*)d_in[5], (const float*)d_in[6],
        (const float*)d_in[7], (const float*)d_in[8],
        (const float*)d_in[9], (const float*)d_in[10],
        (const float*)d_in[11], (const float*)d_in[12],
        (const float*)d_in[13], (const float*)d_in[14],
        (float*)d_out, N);
}

// round 12
// speedup vs baseline: 1.3111x; 1.2124x over previous
#include <cuda_runtime.h>
#include <cuda_fp16.h>
#include <stdint.h>

// OptimizerNetwork: 2-layer LSTM-cell meta-optimizer, N=1e6 rows, H=20.
// Best = R7 (163us): per-warp 32-row slab, HMMA m16n8k16, gate-permuted B,
// register epilogue, bias as GEMM column. R8-R11 latency/occupancy variants
// all neutral: plateau is total GEMM work. R12: bf16 3-pass hi/lo -> fp16
// 2-pass (A split hi/lo, B single fp16; dropped term ~2^-11 -> rel_err ~1e-4).
// MMAs 300->200, GEMM LDS 420->180 per slab. Epilogue/staging = R7 verbatim.

#define TPB 128
typedef unsigned uns;

// ---- smem layout (bytes) ----
#define A_OFF     0u        // [2][128][58] fp16; row stride 116B
#define A_STRIDE  116u
#define A_SPLIT   14848u
#define B1_OFF    29696u    // [80][40] fp16 (hi only); row stride 80B
#define B1_STRIDE 80u
#define B2_OFF    36096u    // [80][56] fp16; row stride 112B
#define B2_STRIDE 112u
#define WOUT_OFF  45056u    // float[20]
#define BOUT_OFF  45136u    // float
#define SMEM_BYTES 45152u

__device__ __forceinline__ float tanha(float x) {
    float r; asm("tanh.approx.f32 %0, %1;" : "=f"(r) : "f"(x)); return r;
}
__device__ __forceinline__ float sigm(float x) {
    return fmaf(0.5f, tanha(0.5f * x), 0.5f);
}

// store float pair as fp16 hi + residual lo into both A splits (col even)
__device__ __forceinline__ void stA2(char* sm, int row, int col, float a, float b) {
    __half ah = __float2half_rn(a), bh = __float2half_rn(b);
    __half2 hv; hv.x = ah; hv.y = bh;
    __half2 lv;
    lv.x = __float2half_rn(a - __half2float(ah));
    lv.y = __float2half_rn(b - __half2float(bh));
    char* p = sm + A_OFF + row * A_STRIDE + col * 2;
    *(__half2*)p = hv;
    *(__half2*)(p + A_SPLIT) = lv;
}
__device__ __forceinline__ void stA1(char* sm, int row, int col, float a) {
    __half h = __float2half_rn(a);
    char* p = sm + A_OFF + row * A_STRIDE + col * 2;
    *(__half*)p = h;
    *(__half*)(p + A_SPLIT) = __float2half_rn(a - __half2float(h));
}
// B: single fp16 (no split)
__device__ __forceinline__ void stB(char* sm, uns off, uns stride,
                                    int row, int col, float v) {
    *(__half*)(sm + off + row * stride + col * 2) = __float2half_rn(v);
}

__device__ __forceinline__ void mma16816(float* c, const uns* a, const uns* b) {
    asm volatile("mma.sync.aligned.m16n8k16.row.col.f32.f16.f16.f32 "
        "{%0,%1,%2,%3}, {%4,%5,%6,%7}, {%8,%9}, {%0,%1,%2,%3};"
        : "+f"(c[0]), "+f"(c[1]), "+f"(c[2]), "+f"(c[3])
        : "r"(a[0]), "r"(a[1]), "r"(a[2]), "r"(a[3]), "r"(b[0]), "r"(b[1]));
}

// A fragment: rows mbase+(l/4), +8; k = kb+(l%4)*2, +8
__device__ __forceinline__ void ldA(uns* a, const char* abase, int mbase, int kb, int l) {
    const char* p = abase + (mbase + (l >> 2)) * A_STRIDE + (kb + (l & 3) * 2) * 2;
    a[0] = *(const uns*)p;
    a[1] = *(const uns*)(p + 8 * A_STRIDE);
    a[2] = *(const uns*)(p + 16);
    a[3] = *(const uns*)(p + 8 * A_STRIDE + 16);
}
__device__ __forceinline__ void ldB(uns* b, const char* bbase, uns stride,
                                    int nbase, int kb, int l) {
    const char* p = bbase + (nbase + (l >> 2)) * stride + (kb + (l & 3) * 2) * 2;
    b[0] = *(const uns*)p;
    b[1] = *(const uns*)(p + 16);
}

// cell GEMM, fp16 2-pass: C = Ah*B + Al*B. A frags loaded once per kstep
// (reused across both splits); B loaded once per (k,n).
template <int KS>
__device__ __forceinline__ void gemm(float C[10][2][4], const char* sm,
                                     uns boff, uns bstride, int wrow, int l) {
#pragma unroll
    for (int n = 0; n < 10; ++n)
#pragma unroll
        for (int m = 0; m < 2; ++m)
#pragma unroll
            for (int q = 0; q < 4; ++q) C[n][m][q] = 0.f;
#pragma unroll
    for (int k = 0; k < KS; ++k) {
        uns ah0[4], ah1[4], al0[4], al1[4];
        ldA(ah0, sm + A_OFF,           wrow,      k * 16, l);
        ldA(ah1, sm + A_OFF,           wrow + 16, k * 16, l);
        ldA(al0, sm + A_OFF + A_SPLIT, wrow,      k * 16, l);
        ldA(al1, sm + A_OFF + A_SPLIT, wrow + 16, k * 16, l);
#pragma unroll
        for (int n = 0; n < 10; ++n) {
            uns b[2];
            ldB(b, sm + boff, bstride, n * 8, k * 16, l);
            mma16816(C[n][0], ah0, b);
            mma16816(C[n][1], ah1, b);
            mma16816(C[n][0], al0, b);
            mma16816(C[n][1], al1, b);
        }
    }
}

__global__ void __launch_bounds__(TPB, 3)
optnet_mma(const float* __restrict__ inp,
           const float* __restrict__ h0g, const float* __restrict__ h1g,
           const float* __restrict__ c0g, const float* __restrict__ c1g,
           const float* __restrict__ Wih1, const float* __restrict__ Whh1,
           const float* __restrict__ bih1, const float* __restrict__ bhh1,
           const float* __restrict__ Wih2, const float* __restrict__ Whh2,
           const float* __restrict__ bih2, const float* __restrict__ bhh2,
           const float* __restrict__ Wout, const float* __restrict__ bout,
           float* __restrict__ out, int N)
{
    extern __shared__ char sm[];
    const int tid = threadIdx.x;
    const int wid = tid >> 5;
    const int l = tid & 31;

    // ---- prologue: zero, stage gate-permuted fp16 weights + consts ----
    for (int i = tid; i < (int)(SMEM_BYTES / 16); i += TPB)
        ((float4*)sm)[i] = make_float4(0.f, 0.f, 0.f, 0.f);
    __syncthreads();

    // B row p: p=2h -> i_h (W row h), 2h+1 -> f_h (20+h),
    //          40+2h -> g_h (40+h), 41+2h -> o_h (60+h)
    if (tid < 80) {
        const int p = tid;
        int h, r;
        if (p < 40) { h = p >> 1; r = (p & 1) ? 20 + h : h; }
        else { int q = p - 40; h = q >> 1; r = (q & 1) ? 60 + h : 40 + h; }
        stB(sm, B1_OFF, B1_STRIDE, p, 0, Wih1[r * 2 + 0]);
        stB(sm, B1_OFF, B1_STRIDE, p, 1, Wih1[r * 2 + 1]);
        for (int k = 0; k < 20; ++k) {
            stB(sm, B1_OFF, B1_STRIDE, p, 2 + k, Whh1[r * 20 + k]);
            stB(sm, B2_OFF, B2_STRIDE, p, k, Wih2[r * 20 + k]);
            stB(sm, B2_OFF, B2_STRIDE, p, 20 + k, Whh2[r * 20 + k]);
        }
        stB(sm, B1_OFF, B1_STRIDE, p, 22, bih1[r] + bhh1[r]);
        stB(sm, B2_OFF, B2_STRIDE, p, 40, bih2[r] + bhh2[r]);
    }
    if (tid < 20) ((float*)(sm + WOUT_OFF))[tid] = Wout[tid];
    if (tid == 0) *(float*)(sm + BOUT_OFF) = bout[0];
    // A bias col 40 (cell2) set once; never overwritten per-slab.
    stA2(sm, (wid << 5) | l, 40, 1.f, 0.f);
    __syncthreads();

    float woutR[5];
#pragma unroll
    for (int j = 0; j < 5; ++j)
        woutR[j] = ((const float*)(sm + WOUT_OFF))[(l & 3) + 4 * j];
    const float boutv = *(const float*)(sm + BOUT_OFF);

    // output tuple sections: out, h0n@N, h1n@21N, c0n@41N, c1n@61N
    float* h0n_out = out + (size_t)N;
    float* h1n_out = out + (size_t)N * 21;
    float* c0n_out = out + (size_t)N * 41;
    float* c1n_out = out + (size_t)N * 61;

    const int wrow = wid * 32;
    const int nslabs = (N + 31) / 32;
    const int twarps = gridDim.x * 4;
    float C[10][2][4];

    for (int s = blockIdx.x * 4 + wid; s < nslabs; s += twarps) {
        const int rowbase = s * 32;

        // ---- stage A cell1: x_pre (0,1), bias (22), h0 (2..21) ----
        {
            const int grow = rowbase + l;
            float x = (grow < N) ? inp[grow] : 0.f;
            float ax = fabsf(x), pa, pb;
            if (ax >= 4.5399930e-05f) {        // exp(-10)
                pa = __logf(ax + 1e-8f) * 0.1f;
                pb = (x > 0.f) ? 1.f : -1.f;
            } else {
                pa = -1.f;
                pb = 22026.4658f * x;          // exp(10)
            }
            stA2(sm, wrow + l, 0, pa, pb);
            stA2(sm, wrow + l, 22, 1.f, 0.f);  // clobbered by h1 staging later
#pragma unroll
            for (int q = 0; q < 5; ++q) {
                const int idx = q * 32 + l;
                const int gr = idx / 5, cp = idx % 5;
                float4 v = make_float4(0.f, 0.f, 0.f, 0.f);
                if (rowbase + gr < N)
                    v = ((const float4*)(h0g + (size_t)rowbase * 20))[idx];
                stA2(sm, wrow + gr, 2 + cp * 4, v.x, v.y);
                stA2(sm, wrow + gr, 4 + cp * 4, v.z, v.w);
            }
        }
        __syncwarp();

        // ---- cell1 GEMM: K=32 ----
        gemm<2>(C, sm, B1_OFF, B1_STRIDE, wrow, l);
        __syncwarp();

        // ---- epilogue 1 + stage h0n (A cols 0..19) ----
#pragma unroll
        for (int rs = 0; rs < 4; ++rs) {
            const int mt = rs >> 1, cb = (rs & 1) * 2;
            const int rloc = (l >> 2) + 8 * rs;
            const size_t grow = (size_t)rowbase + rloc;
            const bool ok = grow < (size_t)N;
#pragma unroll
            for (int j = 0; j < 5; ++j) {
                const int h = (l & 3) + 4 * j;
                float I = sigm(C[j][mt][cb]);
                float F = sigm(C[j][mt][cb + 1]);
                float G = tanha(C[j + 5][mt][cb]);
                float O = sigm(C[j + 5][mt][cb + 1]);
                float cin = ok ? c0g[grow * 20 + h] : 0.f;
                float cn = fmaf(F, cin, I * G);
                float hn = O * tanha(cn);
                if (ok) {
                    c0n_out[grow * 20 + h] = cn;
                    h0n_out[grow * 20 + h] = hn;
                }
                stA1(sm, wrow + rloc, h, hn);
            }
        }
        // stage h1 (cols 20..39); bias col 40 persists from prologue
        {
#pragma unroll
            for (int q = 0; q < 5; ++q) {
                const int idx = q * 32 + l;
                const int gr = idx / 5, cp = idx % 5;
                float4 v = make_float4(0.f, 0.f, 0.f, 0.f);
                if (rowbase + gr < N)
                    v = ((const float4*)(h1g + (size_t)rowbase * 20))[idx];
                stA2(sm, wrow + gr, 20 + cp * 4, v.x, v.y);
                stA2(sm, wrow + gr, 22 + cp * 4, v.z, v.w);
            }
        }
        __syncwarp();

        // ---- cell2 GEMM: K=48 ----
        gemm<3>(C, sm, B2_OFF, B2_STRIDE, wrow, l);

        // ---- epilogue 2: c1n, h1n, out = h1n.Wout + bout ----
#pragma unroll
        for (int rs = 0; rs < 4; ++rs) {
            const int mt = rs >> 1, cb = (rs & 1) * 2;
            const int rloc = (l >> 2) + 8 * rs;
            const size_t grow = (size_t)rowbase + rloc;
            const bool ok = grow < (size_t)N;
            float psum = 0.f;
#pragma unroll
            for (int j = 0; j < 5; ++j) {
                const int h = (l & 3) + 4 * j;
                float I = sigm(C[j][mt][cb]);
                float F = sigm(C[j][mt][cb + 1]);
                float G = tanha(C[j + 5][mt][cb]);
                float O = sigm(C[j + 5][mt][cb + 1]);
                float cin = ok ? c1g[grow * 20 + h] : 0.f;
                float cn = fmaf(F, cin, I * G);
                float hn = O * tanha(cn);
                if (ok) {
                    c1n_out[grow * 20 + h] = cn;
                    h1n_out[grow * 20 + h] = hn;
                }
                psum = fmaf(hn, woutR[j], psum);
            }
            psum += __shfl_xor_sync(0xFFFFFFFFu, psum, 1);
            psum += __shfl_xor_sync(0xFFFFFFFFu, psum, 2);
            if (ok && (l & 3) == 0) out[grow] = psum + boutv;
        }
        __syncwarp();   // before next iteration restages A
    }
}

extern "C" void kernel_launch(void* const* d_in, const int* in_sizes, int n_in,
                              void* d_out, int out_size)
{
    static int configured = 0;
    if (!configured) {
        cudaFuncSetAttribute(optnet_mma,
                             cudaFuncAttributeMaxDynamicSharedMemorySize,
                             SMEM_BYTES);
        configured = 1;
    }
    const int N = in_sizes[0];
    const int grid = 444;   // 3 CTAs/SM x 148 SMs, persistent
    optnet_mma<<<grid, TPB, SMEM_BYTES>>>(
        (const float*)d_in[0], (const float*)d_in[1], (const float*)d_in[2],
        (const float*)d_in[3], (const float*)d_in[4],
        (const float*)d_in[5], (const float*)d_in[6],
        (const float*)d_in[7], (const float*)d_in[8],
        (const float*)d_in[9], (const float*)d_in[10],
        (const float*)d_in[11], (const float*)d_in[12],
        (const float*)d_in[13], (const float*)d_in[14],
        (float*)d_out, N);
}

// round 13
// speedup vs baseline: 1.4164x; 1.0803x over previous
#include <cuda_runtime.h>
#include <cuda_fp16.h>
#include <stdint.h>

// OptimizerNetwork: 2-layer LSTM-cell meta-optimizer, N=1e6 rows, H=20.
// Lineage: R7 HMMA struct (163us) -> R12 fp16 2-pass (138us, rel_err 1.5e-4).
// R13: single-pass fp16 (A and B unsplit). Measured R12 error = B-trunc term
// alone; adding A-trunc of same structure -> ~3e-4, still 3x under 1e-3.
// MMAs 200->100, GEMM LDS halved, staging stores halved, smem 45->30KB.
// Approaching DRAM roofline (648MB I/O, floor ~110us).

#define TPB 128
typedef unsigned uns;

// ---- smem layout (bytes) ----
#define A_OFF     0u        // [128][58] fp16; row stride 116B
#define A_STRIDE  116u
#define B1_OFF    14848u    // [80][40] fp16; row stride 80B
#define B1_STRIDE 80u
#define B2_OFF    21248u    // [80][56] fp16; row stride 112B
#define B2_STRIDE 112u
#define WOUT_OFF  30208u    // float[20]
#define BOUT_OFF  30288u    // float
#define SMEM_BYTES 30304u

__device__ __forceinline__ float tanha(float x) {
    float r; asm("tanh.approx.f32 %0, %1;" : "=f"(r) : "f"(x)); return r;
}
__device__ __forceinline__ float sigm(float x) {
    return fmaf(0.5f, tanha(0.5f * x), 0.5f);
}

// store float pair as fp16 (cols col,col+1; col even)
__device__ __forceinline__ void stA2(char* sm, int row, int col, float a, float b) {
    __half2 hv; hv.x = __float2half_rn(a); hv.y = __float2half_rn(b);
    *(__half2*)(sm + A_OFF + row * A_STRIDE + col * 2) = hv;
}
__device__ __forceinline__ void stA1(char* sm, int row, int col, float a) {
    *(__half*)(sm + A_OFF + row * A_STRIDE + col * 2) = __float2half_rn(a);
}
__device__ __forceinline__ void stB(char* sm, uns off, uns stride,
                                    int row, int col, float v) {
    *(__half*)(sm + off + row * stride + col * 2) = __float2half_rn(v);
}

__device__ __forceinline__ void mma16816(float* c, const uns* a, const uns* b) {
    asm volatile("mma.sync.aligned.m16n8k16.row.col.f32.f16.f16.f32 "
        "{%0,%1,%2,%3}, {%4,%5,%6,%7}, {%8,%9}, {%0,%1,%2,%3};"
        : "+f"(c[0]), "+f"(c[1]), "+f"(c[2]), "+f"(c[3])
        : "r"(a[0]), "r"(a[1]), "r"(a[2]), "r"(a[3]), "r"(b[0]), "r"(b[1]));
}

// A fragment: rows mbase+(l/4), +8; k = kb+(l%4)*2, +8
__device__ __forceinline__ void ldA(uns* a, const char* abase, int mbase, int kb, int l) {
    const char* p = abase + (mbase + (l >> 2)) * A_STRIDE + (kb + (l & 3) * 2) * 2;
    a[0] = *(const uns*)p;
    a[1] = *(const uns*)(p + 8 * A_STRIDE);
    a[2] = *(const uns*)(p + 16);
    a[3] = *(const uns*)(p + 8 * A_STRIDE + 16);
}
__device__ __forceinline__ void ldB(uns* b, const char* bbase, uns stride,
                                    int nbase, int kb, int l) {
    const char* p = bbase + (nbase + (l >> 2)) * stride + (kb + (l & 3) * 2) * 2;
    b[0] = *(const uns*)p;
    b[1] = *(const uns*)(p + 16);
}

// cell GEMM, single-pass fp16: C = A*B. 2 ldA + 10 ldB + 20 MMA per kstep.
template <int KS>
__device__ __forceinline__ void gemm(float C[10][2][4], const char* sm,
                                     uns boff, uns bstride, int wrow, int l) {
#pragma unroll
    for (int n = 0; n < 10; ++n)
#pragma unroll
        for (int m = 0; m < 2; ++m)
#pragma unroll
            for (int q = 0; q < 4; ++q) C[n][m][q] = 0.f;
#pragma unroll
    for (int k = 0; k < KS; ++k) {
        uns a0[4], a1[4];
        ldA(a0, sm + A_OFF, wrow,      k * 16, l);
        ldA(a1, sm + A_OFF, wrow + 16, k * 16, l);
#pragma unroll
        for (int n = 0; n < 10; ++n) {
            uns b[2];
            ldB(b, sm + boff, bstride, n * 8, k * 16, l);
            mma16816(C[n][0], a0, b);
            mma16816(C[n][1], a1, b);
        }
    }
}

__global__ void __launch_bounds__(TPB, 3)
optnet_mma(const float* __restrict__ inp,
           const float* __restrict__ h0g, const float* __restrict__ h1g,
           const float* __restrict__ c0g, const float* __restrict__ c1g,
           const float* __restrict__ Wih1, const float* __restrict__ Whh1,
           const float* __restrict__ bih1, const float* __restrict__ bhh1,
           const float* __restrict__ Wih2, const float* __restrict__ Whh2,
           const float* __restrict__ bih2, const float* __restrict__ bhh2,
           const float* __restrict__ Wout, const float* __restrict__ bout,
           float* __restrict__ out, int N)
{
    extern __shared__ char sm[];
    const int tid = threadIdx.x;
    const int wid = tid >> 5;
    const int l = tid & 31;

    // ---- prologue: zero, stage gate-permuted fp16 weights + consts ----
    for (int i = tid; i < (int)(SMEM_BYTES / 16); i += TPB)
        ((float4*)sm)[i] = make_float4(0.f, 0.f, 0.f, 0.f);
    __syncthreads();

    // B row p: p=2h -> i_h (W row h), 2h+1 -> f_h (20+h),
    //          40+2h -> g_h (40+h), 41+2h -> o_h (60+h)
    if (tid < 80) {
        const int p = tid;
        int h, r;
        if (p < 40) { h = p >> 1; r = (p & 1) ? 20 + h : h; }
        else { int q = p - 40; h = q >> 1; r = (q & 1) ? 60 + h : 40 + h; }
        stB(sm, B1_OFF, B1_STRIDE, p, 0, Wih1[r * 2 + 0]);
        stB(sm, B1_OFF, B1_STRIDE, p, 1, Wih1[r * 2 + 1]);
        for (int k = 0; k < 20; ++k) {
            stB(sm, B1_OFF, B1_STRIDE, p, 2 + k, Whh1[r * 20 + k]);
            stB(sm, B2_OFF, B2_STRIDE, p, k, Wih2[r * 20 + k]);
            stB(sm, B2_OFF, B2_STRIDE, p, 20 + k, Whh2[r * 20 + k]);
        }
        stB(sm, B1_OFF, B1_STRIDE, p, 22, bih1[r] + bhh1[r]);
        stB(sm, B2_OFF, B2_STRIDE, p, 40, bih2[r] + bhh2[r]);
    }
    if (tid < 20) ((float*)(sm + WOUT_OFF))[tid] = Wout[tid];
    if (tid == 0) *(float*)(sm + BOUT_OFF) = bout[0];
    // A bias col 40 (cell2) set once; never overwritten per-slab.
    stA2(sm, (wid << 5) | l, 40, 1.f, 0.f);
    __syncthreads();

    float woutR[5];
#pragma unroll
    for (int j = 0; j < 5; ++j)
        woutR[j] = ((const float*)(sm + WOUT_OFF))[(l & 3) + 4 * j];
    const float boutv = *(const float*)(sm + BOUT_OFF);

    // output tuple sections: out, h0n@N, h1n@21N, c0n@41N, c1n@61N
    float* h0n_out = out + (size_t)N;
    float* h1n_out = out + (size_t)N * 21;
    float* c0n_out = out + (size_t)N * 41;
    float* c1n_out = out + (size_t)N * 61;

    const int wrow = wid * 32;
    const int nslabs = (N + 31) / 32;
    const int twarps = gridDim.x * 4;
    float C[10][2][4];

    for (int s = blockIdx.x * 4 + wid; s < nslabs; s += twarps) {
        const int rowbase = s * 32;

        // ---- stage A cell1: x_pre (0,1), bias (22), h0 (2..21) ----
        {
            const int grow = rowbase + l;
            float x = (grow < N) ? inp[grow] : 0.f;
            float ax = fabsf(x), pa, pb;
            if (ax >= 4.5399930e-05f) {        // exp(-10)
                pa = __logf(ax + 1e-8f) * 0.1f;
                pb = (x > 0.f) ? 1.f : -1.f;
            } else {
                pa = -1.f;
                pb = 22026.4658f * x;          // exp(10)
            }
            stA2(sm, wrow + l, 0, pa, pb);
            stA2(sm, wrow + l, 22, 1.f, 0.f);  // clobbered by h1 staging later
#pragma unroll
            for (int q = 0; q < 5; ++q) {
                const int idx = q * 32 + l;
                const int gr = idx / 5, cp = idx % 5;
                float4 v = make_float4(0.f, 0.f, 0.f, 0.f);
                if (rowbase + gr < N)
                    v = ((const float4*)(h0g + (size_t)rowbase * 20))[idx];
                stA2(sm, wrow + gr, 2 + cp * 4, v.x, v.y);
                stA2(sm, wrow + gr, 4 + cp * 4, v.z, v.w);
            }
        }
        __syncwarp();

        // ---- cell1 GEMM: K=32 ----
        gemm<2>(C, sm, B1_OFF, B1_STRIDE, wrow, l);
        __syncwarp();

        // ---- epilogue 1 + stage h0n (A cols 0..19) ----
#pragma unroll
        for (int rs = 0; rs < 4; ++rs) {
            const int mt = rs >> 1, cb = (rs & 1) * 2;
            const int rloc = (l >> 2) + 8 * rs;
            const size_t grow = (size_t)rowbase + rloc;
            const bool ok = grow < (size_t)N;
#pragma unroll
            for (int j = 0; j < 5; ++j) {
                const int h = (l & 3) + 4 * j;
                float I = sigm(C[j][mt][cb]);
                float F = sigm(C[j][mt][cb + 1]);
                float G = tanha(C[j + 5][mt][cb]);
                float O = sigm(C[j + 5][mt][cb + 1]);
                float cin = ok ? c0g[grow * 20 + h] : 0.f;
                float cn = fmaf(F, cin, I * G);
                float hn = O * tanha(cn);
                if (ok) {
                    c0n_out[grow * 20 + h] = cn;
                    h0n_out[grow * 20 + h] = hn;
                }
                stA1(sm, wrow + rloc, h, hn);
            }
        }
        // stage h1 (cols 20..39); bias col 40 persists from prologue
        {
#pragma unroll
            for (int q = 0; q < 5; ++q) {
                const int idx = q * 32 + l;
                const int gr = idx / 5, cp = idx % 5;
                float4 v = make_float4(0.f, 0.f, 0.f, 0.f);
                if (rowbase + gr < N)
                    v = ((const float4*)(h1g + (size_t)rowbase * 20))[idx];
                stA2(sm, wrow + gr, 20 + cp * 4, v.x, v.y);
                stA2(sm, wrow + gr, 22 + cp * 4, v.z, v.w);
            }
        }
        __syncwarp();

        // ---- cell2 GEMM: K=48 ----
        gemm<3>(C, sm, B2_OFF, B2_STRIDE, wrow, l);

        // ---- epilogue 2: c1n, h1n, out = h1n.Wout + bout ----
#pragma unroll
        for (int rs = 0; rs < 4; ++rs) {
            const int mt = rs >> 1, cb = (rs & 1) * 2;
            const int rloc = (l >> 2) + 8 * rs;
            const size_t grow = (size_t)rowbase + rloc;
            const bool ok = grow < (size_t)N;
            float psum = 0.f;
#pragma unroll
            for (int j = 0; j < 5; ++j) {
                const int h = (l & 3) + 4 * j;
                float I = sigm(C[j][mt][cb]);
                float F = sigm(C[j][mt][cb + 1]);
                float G = tanha(C[j + 5][mt][cb]);
                float O = sigm(C[j + 5][mt][cb + 1]);
                float cin = ok ? c1g[grow * 20 + h] : 0.f;
                float cn = fmaf(F, cin, I * G);
                float hn = O * tanha(cn);
                if (ok) {
                    c1n_out[grow * 20 + h] = cn;
                    h1n_out[grow * 20 + h] = hn;
                }
                psum = fmaf(hn, woutR[j], psum);
            }
            psum += __shfl_xor_sync(0xFFFFFFFFu, psum, 1);
            psum += __shfl_xor_sync(0xFFFFFFFFu, psum, 2);
            if (ok && (l & 3) == 0) out[grow] = psum + boutv;
        }
        __syncwarp();   // before next iteration restages A
    }
}

extern "C" void kernel_launch(void* const* d_in, const int* in_sizes, int n_in,
                              void* d_out, int out_size)
{
    static int configured = 0;
    if (!configured) {
        cudaFuncSetAttribute(optnet_mma,
                             cudaFuncAttributeMaxDynamicSharedMemorySize,
                             SMEM_BYTES);
        configured = 1;
    }
    const int N = in_sizes[0];
    const int grid = 444;   // 3 CTAs/SM x 148 SMs, persistent
    optnet_mma<<<grid, TPB, SMEM_BYTES>>>(
        (const float*)d_in[0], (const float*)d_in[1], (const float*)d_in[2],
        (const float*)d_in[3], (const float*)d_in[4],
        (const float*)d_in[5], (const float*)d_in[6],
        (const float*)d_in[7], (const float*)d_in[8],
        (const float*)d_in[9], (const float*)d_in[10],
        (const float*)d_in[11], (const float*)d_in[12],
        (const float*)d_in[13], (const float*)d_in[14],
        (float*)d_out, N);
}

// round 14
// speedup vs baseline: 1.4765x; 1.0424x over previous
#include <cuda_runtime.h>
#include <cuda_fp16.h>
#include <stdint.h>

// OptimizerNetwork: 2-layer LSTM-cell meta-optimizer, N=1e6 rows, H=20.
// Lineage: R7 HMMA struct -> R12 fp16 2-pass -> R13 single-pass fp16 (127.5us,
// rel_err 1.65e-4). R13 left: DRAM 60%, occ 17.6% (167 regs: 80 = C accums),
// latency-bound ~20% above the ~108us BW floor. R14: split each cell GEMM
// into two 16-row halves (C[10][4] = 40 regs live), epilogue per half ->
// regs fit 128 -> 4 CTAs/SM (16 warps). B LDS doubles (L1 has headroom).

#define TPB 128
typedef unsigned uns;

// ---- smem layout (bytes) ----
#define A_OFF     0u        // [128][58] fp16; row stride 116B
#define A_STRIDE  116u
#define B1_OFF    14848u    // [80][40] fp16; row stride 80B
#define B1_STRIDE 80u
#define B2_OFF    21248u    // [80][56] fp16; row stride 112B
#define B2_STRIDE 112u
#define WOUT_OFF  30208u    // float[20]
#define BOUT_OFF  30288u    // float
#define SMEM_BYTES 30304u

__device__ __forceinline__ float tanha(float x) {
    float r; asm("tanh.approx.f32 %0, %1;" : "=f"(r) : "f"(x)); return r;
}
__device__ __forceinline__ float sigm(float x) {
    return fmaf(0.5f, tanha(0.5f * x), 0.5f);
}

// store float pair as fp16 (cols col,col+1; col even)
__device__ __forceinline__ void stA2(char* sm, int row, int col, float a, float b) {
    __half2 hv; hv.x = __float2half_rn(a); hv.y = __float2half_rn(b);
    *(__half2*)(sm + A_OFF + row * A_STRIDE + col * 2) = hv;
}
__device__ __forceinline__ void stA1(char* sm, int row, int col, float a) {
    *(__half*)(sm + A_OFF + row * A_STRIDE + col * 2) = __float2half_rn(a);
}
__device__ __forceinline__ void stB(char* sm, uns off, uns stride,
                                    int row, int col, float v) {
    *(__half*)(sm + off + row * stride + col * 2) = __float2half_rn(v);
}

__device__ __forceinline__ void mma16816(float* c, const uns* a, const uns* b) {
    asm volatile("mma.sync.aligned.m16n8k16.row.col.f32.f16.f16.f32 "
        "{%0,%1,%2,%3}, {%4,%5,%6,%7}, {%8,%9}, {%0,%1,%2,%3};"
        : "+f"(c[0]), "+f"(c[1]), "+f"(c[2]), "+f"(c[3])
        : "r"(a[0]), "r"(a[1]), "r"(a[2]), "r"(a[3]), "r"(b[0]), "r"(b[1]));
}

// A fragment: rows mbase+(l/4), +8; k = kb+(l%4)*2, +8
__device__ __forceinline__ void ldA(uns* a, const char* abase, int mbase, int kb, int l) {
    const char* p = abase + (mbase + (l >> 2)) * A_STRIDE + (kb + (l & 3) * 2) * 2;
    a[0] = *(const uns*)p;
    a[1] = *(const uns*)(p + 8 * A_STRIDE);
    a[2] = *(const uns*)(p + 16);
    a[3] = *(const uns*)(p + 8 * A_STRIDE + 16);
}
__device__ __forceinline__ void ldB(uns* b, const char* bbase, uns stride,
                                    int nbase, int kb, int l) {
    const char* p = bbase + (nbase + (l >> 2)) * stride + (kb + (l & 3) * 2) * 2;
    b[0] = *(const uns*)p;
    b[1] = *(const uns*)(p + 16);
}

// half-slab GEMM (16 rows): C[10][4] = A[mrow..mrow+15, :] * B
template <int KS>
__device__ __forceinline__ void gemm_half(float C[10][4], const char* sm,
                                          uns boff, uns bstride, int mrow, int l) {
#pragma unroll
    for (int n = 0; n < 10; ++n)
#pragma unroll
        for (int q = 0; q < 4; ++q) C[n][q] = 0.f;
#pragma unroll
    for (int k = 0; k < KS; ++k) {
        uns a0[4];
        ldA(a0, sm + A_OFF, mrow, k * 16, l);
#pragma unroll
        for (int n = 0; n < 10; ++n) {
            uns b[2];
            ldB(b, sm + boff, bstride, n * 8, k * 16, l);
            mma16816(C[n], a0, b);
        }
    }
}

__global__ void __launch_bounds__(TPB, 4)
optnet_mma(const float* __restrict__ inp,
           const float* __restrict__ h0g, const float* __restrict__ h1g,
           const float* __restrict__ c0g, const float* __restrict__ c1g,
           const float* __restrict__ Wih1, const float* __restrict__ Whh1,
           const float* __restrict__ bih1, const float* __restrict__ bhh1,
           const float* __restrict__ Wih2, const float* __restrict__ Whh2,
           const float* __restrict__ bih2, const float* __restrict__ bhh2,
           const float* __restrict__ Wout, const float* __restrict__ bout,
           float* __restrict__ out, int N)
{
    extern __shared__ char sm[];
    const int tid = threadIdx.x;
    const int wid = tid >> 5;
    const int l = tid & 31;

    // ---- prologue: zero, stage gate-permuted fp16 weights + consts ----
    for (int i = tid; i < (int)(SMEM_BYTES / 16); i += TPB)
        ((float4*)sm)[i] = make_float4(0.f, 0.f, 0.f, 0.f);
    __syncthreads();

    // B row p: p=2h -> i_h (W row h), 2h+1 -> f_h (20+h),
    //          40+2h -> g_h (40+h), 41+2h -> o_h (60+h)
    if (tid < 80) {
        const int p = tid;
        int h, r;
        if (p < 40) { h = p >> 1; r = (p & 1) ? 20 + h : h; }
        else { int q = p - 40; h = q >> 1; r = (q & 1) ? 60 + h : 40 + h; }
        stB(sm, B1_OFF, B1_STRIDE, p, 0, Wih1[r * 2 + 0]);
        stB(sm, B1_OFF, B1_STRIDE, p, 1, Wih1[r * 2 + 1]);
        for (int k = 0; k < 20; ++k) {
            stB(sm, B1_OFF, B1_STRIDE, p, 2 + k, Whh1[r * 20 + k]);
            stB(sm, B2_OFF, B2_STRIDE, p, k, Wih2[r * 20 + k]);
            stB(sm, B2_OFF, B2_STRIDE, p, 20 + k, Whh2[r * 20 + k]);
        }
        stB(sm, B1_OFF, B1_STRIDE, p, 22, bih1[r] + bhh1[r]);
        stB(sm, B2_OFF, B2_STRIDE, p, 40, bih2[r] + bhh2[r]);
    }
    if (tid < 20) ((float*)(sm + WOUT_OFF))[tid] = Wout[tid];
    if (tid == 0) *(float*)(sm + BOUT_OFF) = bout[0];
    // A bias col 40 (cell2) set once; never overwritten per-slab.
    stA2(sm, (wid << 5) | l, 40, 1.f, 0.f);
    __syncthreads();

    float woutR[5];
#pragma unroll
    for (int j = 0; j < 5; ++j)
        woutR[j] = ((const float*)(sm + WOUT_OFF))[(l & 3) + 4 * j];
    const float boutv = *(const float*)(sm + BOUT_OFF);

    // output tuple sections: out, h0n@N, h1n@21N, c0n@41N, c1n@61N
    float* h0n_out = out + (size_t)N;
    float* h1n_out = out + (size_t)N * 21;
    float* c0n_out = out + (size_t)N * 41;
    float* c1n_out = out + (size_t)N * 61;

    const int wrow = wid * 32;
    const int nslabs = (N + 31) / 32;
    const int twarps = gridDim.x * 4;
    float C[10][4];

    for (int s = blockIdx.x * 4 + wid; s < nslabs; s += twarps) {
        const int rowbase = s * 32;

        // ---- stage A cell1: x_pre (0,1), bias (22), h0 (2..21) ----
        {
            const int grow = rowbase + l;
            float x = (grow < N) ? inp[grow] : 0.f;
            float ax = fabsf(x), pa, pb;
            if (ax >= 4.5399930e-05f) {        // exp(-10)
                pa = __logf(ax + 1e-8f) * 0.1f;
                pb = (x > 0.f) ? 1.f : -1.f;
            } else {
                pa = -1.f;
                pb = 22026.4658f * x;          // exp(10)
            }
            stA2(sm, wrow + l, 0, pa, pb);
            stA2(sm, wrow + l, 22, 1.f, 0.f);  // clobbered by h1 staging later
#pragma unroll
            for (int q = 0; q < 5; ++q) {
                const int idx = q * 32 + l;
                const int gr = idx / 5, cp = idx % 5;
                float4 v = make_float4(0.f, 0.f, 0.f, 0.f);
                if (rowbase + gr < N)
                    v = ((const float4*)(h0g + (size_t)rowbase * 20))[idx];
                stA2(sm, wrow + gr, 2 + cp * 4, v.x, v.y);
                stA2(sm, wrow + gr, 4 + cp * 4, v.z, v.w);
            }
        }
        __syncwarp();

        // ---- cell1: two 16-row halves ----
#pragma unroll
        for (int mt = 0; mt < 2; ++mt) {
            gemm_half<2>(C, sm, B1_OFF, B1_STRIDE, wrow + 16 * mt, l);
            __syncwarp();
#pragma unroll
            for (int r = 0; r < 2; ++r) {                 // cb = 2r
                const int cb = r * 2;
                const int rloc = (l >> 2) + 16 * mt + 8 * r;
                const size_t grow = (size_t)rowbase + rloc;
                const bool ok = grow < (size_t)N;
#pragma unroll
                for (int j = 0; j < 5; ++j) {
                    const int h = (l & 3) + 4 * j;
                    float I = sigm(C[j][cb]);
                    float F = sigm(C[j][cb + 1]);
                    float G = tanha(C[j + 5][cb]);
                    float O = sigm(C[j + 5][cb + 1]);
                    float cin = ok ? c0g[grow * 20 + h] : 0.f;
                    float cn = fmaf(F, cin, I * G);
                    float hn = O * tanha(cn);
                    if (ok) {
                        c0n_out[grow * 20 + h] = cn;
                        h0n_out[grow * 20 + h] = hn;
                    }
                    stA1(sm, wrow + rloc, h, hn);         // cell2 A cols 0..19
                }
            }
            __syncwarp();
        }

        // ---- stage h1 (cols 20..39); bias col 40 persists ----
#pragma unroll
        for (int q = 0; q < 5; ++q) {
            const int idx = q * 32 + l;
            const int gr = idx / 5, cp = idx % 5;
            float4 v = make_float4(0.f, 0.f, 0.f, 0.f);
            if (rowbase + gr < N)
                v = ((const float4*)(h1g + (size_t)rowbase * 20))[idx];
            stA2(sm, wrow + gr, 20 + cp * 4, v.x, v.y);
            stA2(sm, wrow + gr, 22 + cp * 4, v.z, v.w);
        }
        __syncwarp();

        // ---- cell2: two 16-row halves; fold output dot ----
#pragma unroll
        for (int mt = 0; mt < 2; ++mt) {
            gemm_half<3>(C, sm, B2_OFF, B2_STRIDE, wrow + 16 * mt, l);
            __syncwarp();
#pragma unroll
            for (int r = 0; r < 2; ++r) {
                const int cb = r * 2;
                const int rloc = (l >> 2) + 16 * mt + 8 * r;
                const size_t grow = (size_t)rowbase + rloc;
                const bool ok = grow < (size_t)N;
                float psum = 0.f;
#pragma unroll
                for (int j = 0; j < 5; ++j) {
                    const int h = (l & 3) + 4 * j;
                    float I = sigm(C[j][cb]);
                    float F = sigm(C[j][cb + 1]);
                    float G = tanha(C[j + 5][cb]);
                    float O = sigm(C[j + 5][cb + 1]);
                    float cin = ok ? c1g[grow * 20 + h] : 0.f;
                    float cn = fmaf(F, cin, I * G);
                    float hn = O * tanha(cn);
                    if (ok) {
                        c1n_out[grow * 20 + h] = cn;
                        h1n_out[grow * 20 + h] = hn;
                    }
                    psum = fmaf(hn, woutR[j], psum);
                }
                psum += __shfl_xor_sync(0xFFFFFFFFu, psum, 1);
                psum += __shfl_xor_sync(0xFFFFFFFFu, psum, 2);
                if (ok && (l & 3) == 0) out[grow] = psum + boutv;
            }
            __syncwarp();
        }
    }
}

extern "C" void kernel_launch(void* const* d_in, const int* in_sizes, int n_in,
                              void* d_out, int out_size)
{
    static int configured = 0;
    if (!configured) {
        cudaFuncSetAttribute(optnet_mma,
                             cudaFuncAttributeMaxDynamicSharedMemorySize,
                             SMEM_BYTES);
        configured = 1;
    }
    const int N = in_sizes[0];
    const int grid = 592;   // 4 CTAs/SM x 148 SMs, persistent
    optnet_mma<<<grid, TPB, SMEM_BYTES>>>(
        (const float*)d_in[0], (const float*)d_in[1], (const float*)d_in[2],
        (const float*)d_in[3], (const float*)d_in[4],
        (const float*)d_in[5], (const float*)d_in[6],
        (const float*)d_in[7], (const float*)d_in[8],
        (const float*)d_in[9], (const float*)d_in[10],
        (const float*)d_in[11], (const float*)d_in[12],
        (const float*)d_in[13], (const float*)d_in[14],
        (float*)d_out, N);
}

// round 15
// speedup vs baseline: 1.4881x; 1.0079x over previous
#include <cuda_runtime.h>
#include <cuda_fp16.h>
#include <stdint.h>

// OptimizerNetwork: 2-layer LSTM-cell meta-optimizer, N=1e6 rows, H=20.
// Lineage: R7 HMMA struct -> R12/R13 fp16 precision cuts -> R14 mt-split
// epilogue (122.3us, 127 regs, 4 CTAs/SM, DRAM 62.8%). Regime: DRAM-latency
// bound; request rate scales with resident warps. R15: launch_bounds(128,5)
// (cap 102 regs; spills land on cold staging temps) + grid 740 -> 20 warps/SM.

#define TPB 128
typedef unsigned uns;

// ---- smem layout (bytes) ----
#define A_OFF     0u        // [128][58] fp16; row stride 116B
#define A_STRIDE  116u
#define B1_OFF    14848u    // [80][40] fp16; row stride 80B
#define B1_STRIDE 80u
#define B2_OFF    21248u    // [80][56] fp16; row stride 112B
#define B2_STRIDE 112u
#define WOUT_OFF  30208u    // float[20]
#define BOUT_OFF  30288u    // float
#define SMEM_BYTES 30304u

__device__ __forceinline__ float tanha(float x) {
    float r; asm("tanh.approx.f32 %0, %1;" : "=f"(r) : "f"(x)); return r;
}
__device__ __forceinline__ float sigm(float x) {
    return fmaf(0.5f, tanha(0.5f * x), 0.5f);
}

// store float pair as fp16 (cols col,col+1; col even)
__device__ __forceinline__ void stA2(char* sm, int row, int col, float a, float b) {
    __half2 hv; hv.x = __float2half_rn(a); hv.y = __float2half_rn(b);
    *(__half2*)(sm + A_OFF + row * A_STRIDE + col * 2) = hv;
}
__device__ __forceinline__ void stA1(char* sm, int row, int col, float a) {
    *(__half*)(sm + A_OFF + row * A_STRIDE + col * 2) = __float2half_rn(a);
}
__device__ __forceinline__ void stB(char* sm, uns off, uns stride,
                                    int row, int col, float v) {
    *(__half*)(sm + off + row * stride + col * 2) = __float2half_rn(v);
}

__device__ __forceinline__ void mma16816(float* c, const uns* a, const uns* b) {
    asm volatile("mma.sync.aligned.m16n8k16.row.col.f32.f16.f16.f32 "
        "{%0,%1,%2,%3}, {%4,%5,%6,%7}, {%8,%9}, {%0,%1,%2,%3};"
        : "+f"(c[0]), "+f"(c[1]), "+f"(c[2]), "+f"(c[3])
        : "r"(a[0]), "r"(a[1]), "r"(a[2]), "r"(a[3]), "r"(b[0]), "r"(b[1]));
}

// A fragment: rows mbase+(l/4), +8; k = kb+(l%4)*2, +8
__device__ __forceinline__ void ldA(uns* a, const char* abase, int mbase, int kb, int l) {
    const char* p = abase + (mbase + (l >> 2)) * A_STRIDE + (kb + (l & 3) * 2) * 2;
    a[0] = *(const uns*)p;
    a[1] = *(const uns*)(p + 8 * A_STRIDE);
    a[2] = *(const uns*)(p + 16);
    a[3] = *(const uns*)(p + 8 * A_STRIDE + 16);
}
__device__ __forceinline__ void ldB(uns* b, const char* bbase, uns stride,
                                    int nbase, int kb, int l) {
    const char* p = bbase + (nbase + (l >> 2)) * stride + (kb + (l & 3) * 2) * 2;
    b[0] = *(const uns*)p;
    b[1] = *(const uns*)(p + 16);
}

// half-slab GEMM (16 rows): C[10][4] = A[mrow..mrow+15, :] * B
template <int KS>
__device__ __forceinline__ void gemm_half(float C[10][4], const char* sm,
                                          uns boff, uns bstride, int mrow, int l) {
#pragma unroll
    for (int n = 0; n < 10; ++n)
#pragma unroll
        for (int q = 0; q < 4; ++q) C[n][q] = 0.f;
#pragma unroll
    for (int k = 0; k < KS; ++k) {
        uns a0[4];
        ldA(a0, sm + A_OFF, mrow, k * 16, l);
#pragma unroll
        for (int n = 0; n < 10; ++n) {
            uns b[2];
            ldB(b, sm + boff, bstride, n * 8, k * 16, l);
            mma16816(C[n], a0, b);
        }
    }
}

__global__ void __launch_bounds__(TPB, 5)
optnet_mma(const float* __restrict__ inp,
           const float* __restrict__ h0g, const float* __restrict__ h1g,
           const float* __restrict__ c0g, const float* __restrict__ c1g,
           const float* __restrict__ Wih1, const float* __restrict__ Whh1,
           const float* __restrict__ bih1, const float* __restrict__ bhh1,
           const float* __restrict__ Wih2, const float* __restrict__ Whh2,
           const float* __restrict__ bih2, const float* __restrict__ bhh2,
           const float* __restrict__ Wout, const float* __restrict__ bout,
           float* __restrict__ out, int N)
{
    extern __shared__ char sm[];
    const int tid = threadIdx.x;
    const int wid = tid >> 5;
    const int l = tid & 31;

    // ---- prologue: zero, stage gate-permuted fp16 weights + consts ----
    for (int i = tid; i < (int)(SMEM_BYTES / 16); i += TPB)
        ((float4*)sm)[i] = make_float4(0.f, 0.f, 0.f, 0.f);
    __syncthreads();

    // B row p: p=2h -> i_h (W row h), 2h+1 -> f_h (20+h),
    //          40+2h -> g_h (40+h), 41+2h -> o_h (60+h)
    if (tid < 80) {
        const int p = tid;
        int h, r;
        if (p < 40) { h = p >> 1; r = (p & 1) ? 20 + h : h; }
        else { int q = p - 40; h = q >> 1; r = (q & 1) ? 60 + h : 40 + h; }
        stB(sm, B1_OFF, B1_STRIDE, p, 0, Wih1[r * 2 + 0]);
        stB(sm, B1_OFF, B1_STRIDE, p, 1, Wih1[r * 2 + 1]);
        for (int k = 0; k < 20; ++k) {
            stB(sm, B1_OFF, B1_STRIDE, p, 2 + k, Whh1[r * 20 + k]);
            stB(sm, B2_OFF, B2_STRIDE, p, k, Wih2[r * 20 + k]);
            stB(sm, B2_OFF, B2_STRIDE, p, 20 + k, Whh2[r * 20 + k]);
        }
        stB(sm, B1_OFF, B1_STRIDE, p, 22, bih1[r] + bhh1[r]);
        stB(sm, B2_OFF, B2_STRIDE, p, 40, bih2[r] + bhh2[r]);
    }
    if (tid < 20) ((float*)(sm + WOUT_OFF))[tid] = Wout[tid];
    if (tid == 0) *(float*)(sm + BOUT_OFF) = bout[0];
    // A bias col 40 (cell2) set once; never overwritten per-slab.
    stA2(sm, (wid << 5) | l, 40, 1.f, 0.f);
    __syncthreads();

    float woutR[5];
#pragma unroll
    for (int j = 0; j < 5; ++j)
        woutR[j] = ((const float*)(sm + WOUT_OFF))[(l & 3) + 4 * j];
    const float boutv = *(const float*)(sm + BOUT_OFF);

    // output tuple sections: out, h0n@N, h1n@21N, c0n@41N, c1n@61N
    float* h0n_out = out + (size_t)N;
    float* h1n_out = out + (size_t)N * 21;
    float* c0n_out = out + (size_t)N * 41;
    float* c1n_out = out + (size_t)N * 61;

    const int wrow = wid * 32;
    const int nslabs = (N + 31) / 32;
    const int twarps = gridDim.x * 4;
    float C[10][4];

    for (int s = blockIdx.x * 4 + wid; s < nslabs; s += twarps) {
        const int rowbase = s * 32;

        // ---- stage A cell1: x_pre (0,1), bias (22), h0 (2..21) ----
        {
            const int grow = rowbase + l;
            float x = (grow < N) ? inp[grow] : 0.f;
            float ax = fabsf(x), pa, pb;
            if (ax >= 4.5399930e-05f) {        // exp(-10)
                pa = __logf(ax + 1e-8f) * 0.1f;
                pb = (x > 0.f) ? 1.f : -1.f;
            } else {
                pa = -1.f;
                pb = 22026.4658f * x;          // exp(10)
            }
            stA2(sm, wrow + l, 0, pa, pb);
            stA2(sm, wrow + l, 22, 1.f, 0.f);  // clobbered by h1 staging later
#pragma unroll
            for (int q = 0; q < 5; ++q) {
                const int idx = q * 32 + l;
                const int gr = idx / 5, cp = idx % 5;
                float4 v = make_float4(0.f, 0.f, 0.f, 0.f);
                if (rowbase + gr < N)
                    v = ((const float4*)(h0g + (size_t)rowbase * 20))[idx];
                stA2(sm, wrow + gr, 2 + cp * 4, v.x, v.y);
                stA2(sm, wrow + gr, 4 + cp * 4, v.z, v.w);
            }
        }
        __syncwarp();

        // ---- cell1: two 16-row halves ----
#pragma unroll
        for (int mt = 0; mt < 2; ++mt) {
            gemm_half<2>(C, sm, B1_OFF, B1_STRIDE, wrow + 16 * mt, l);
            __syncwarp();
#pragma unroll
            for (int r = 0; r < 2; ++r) {                 // cb = 2r
                const int cb = r * 2;
                const int rloc = (l >> 2) + 16 * mt + 8 * r;
                const size_t grow = (size_t)rowbase + rloc;
                const bool ok = grow < (size_t)N;
#pragma unroll
                for (int j = 0; j < 5; ++j) {
                    const int h = (l & 3) + 4 * j;
                    float I = sigm(C[j][cb]);
                    float F = sigm(C[j][cb + 1]);
                    float G = tanha(C[j + 5][cb]);
                    float O = sigm(C[j + 5][cb + 1]);
                    float cin = ok ? c0g[grow * 20 + h] : 0.f;
                    float cn = fmaf(F, cin, I * G);
                    float hn = O * tanha(cn);
                    if (ok) {
                        c0n_out[grow * 20 + h] = cn;
                        h0n_out[grow * 20 + h] = hn;
                    }
                    stA1(sm, wrow + rloc, h, hn);         // cell2 A cols 0..19
                }
            }
            __syncwarp();
        }

        // ---- stage h1 (cols 20..39); bias col 40 persists ----
#pragma unroll
        for (int q = 0; q < 5; ++q) {
            const int idx = q * 32 + l;
            const int gr = idx / 5, cp = idx % 5;
            float4 v = make_float4(0.f, 0.f, 0.f, 0.f);
            if (rowbase + gr < N)
                v = ((const float4*)(h1g + (size_t)rowbase * 20))[idx];
            stA2(sm, wrow + gr, 20 + cp * 4, v.x, v.y);
            stA2(sm, wrow + gr, 22 + cp * 4, v.z, v.w);
        }
        __syncwarp();

        // ---- cell2: two 16-row halves; fold output dot ----
#pragma unroll
        for (int mt = 0; mt < 2; ++mt) {
            gemm_half<3>(C, sm, B2_OFF, B2_STRIDE, wrow + 16 * mt, l);
            __syncwarp();
#pragma unroll
            for (int r = 0; r < 2; ++r) {
                const int cb = r * 2;
                const int rloc = (l >> 2) + 16 * mt + 8 * r;
                const size_t grow = (size_t)rowbase + rloc;
                const bool ok = grow < (size_t)N;
                float psum = 0.f;
#pragma unroll
                for (int j = 0; j < 5; ++j) {
                    const int h = (l & 3) + 4 * j;
                    float I = sigm(C[j][cb]);
                    float F = sigm(C[j][cb + 1]);
                    float G = tanha(C[j + 5][cb]);
                    float O = sigm(C[j + 5][cb + 1]);
                    float cin = ok ? c1g[grow * 20 + h] : 0.f;
                    float cn = fmaf(F, cin, I * G);
                    float hn = O * tanha(cn);
                    if (ok) {
                        c1n_out[grow * 20 + h] = cn;
                        h1n_out[grow * 20 + h] = hn;
                    }
                    psum = fmaf(hn, woutR[j], psum);
                }
                psum += __shfl_xor_sync(0xFFFFFFFFu, psum, 1);
                psum += __shfl_xor_sync(0xFFFFFFFFu, psum, 2);
                if (ok && (l & 3) == 0) out[grow] = psum + boutv;
            }
            __syncwarp();
        }
    }
}

extern "C" void kernel_launch(void* const* d_in, const int* in_sizes, int n_in,
                              void* d_out, int out_size)
{
    static int configured = 0;
    if (!configured) {
        cudaFuncSetAttribute(optnet_mma,
                             cudaFuncAttributeMaxDynamicSharedMemorySize,
                             SMEM_BYTES);
        configured = 1;
    }
    const int N = in_sizes[0];
    const int grid = 740;   // 5 CTAs/SM x 148 SMs, persistent
    optnet_mma<<<grid, TPB, SMEM_BYTES>>>(
        (const float*)d_in[0], (const float*)d_in[1], (const float*)d_in[2],
        (const float*)d_in[3], (const float*)d_in[4],
        (const float*)d_in[5], (const float*)d_in[6],
        (const float*)d_in[7], (const float*)d_in[8],
        (const float*)d_in[9], (const float*)d_in[10],
        (const float*)d_in[11], (const float*)d_in[12],
        (const float*)d_in[13], (const float*)d_in[14],
        (float*)d_out, N);
}